// round 15
// baseline (speedup 1.0000x reference)
#include <cuda_runtime.h>
#include <cuda_fp16.h>

#define B 512
#define D 128
#define JT 64            // j per work unit
#define NBLK 444         // persistent grid: 148 SMs x 3 blocks
#define NUNIT 4096       // (512 i) x (8 j-tiles)

// ---------------- device scratch (no allocation allowed) ----------------
__device__ float  g_e1n[3][B][D];     // normalized emb1, row-major [l][i][d]
__device__ __half g_e2nTh[3][D][B];   // normalized emb2, fp16, transposed [l][d][j]
__device__ float  g_c1p[2][B][D];     // cert1_{1,2} * 0.5*alpha_{1,2}
__device__ __half g_c2Th[2][D][B];    // cert2_{1,2}, fp16, transposed [l][d][j]
__device__ float  g_bp[2][D];         // 0.5*beta_{1,2}
__device__ uint4  g_wH[2][D];         // .x/.y/.z = broadcast half2 of w0..w2, .w = packed idx
__device__ unsigned g_arrive = 0;     // device-wide barrier: arrival counter
__device__ unsigned g_release = 0;    // device-wide barrier: monotonic epoch

__device__ __forceinline__ __half2 u2h(unsigned x) {
    __half2 h; *(unsigned*)&h = x; return h;
}
__device__ __forceinline__ unsigned h2u(__half2 h) {
    return *(unsigned*)&h;
}
__device__ __forceinline__ __half2 tanh2(__half2 x) {
    unsigned xi = h2u(x), yo;
    asm("tanh.approx.f16x2 %0, %1;" : "=r"(yo) : "r"(xi));
    return u2h(yo);
}
// r = s + P*(n-s),  n = (a-e2)^2,  P = 0.5*tanh(cp*c2+bp)+0.5   (all half2)
__device__ __forceinline__ __half2 blend2(__half2 ha, __half2 e2, __half2 cp,
                                          __half2 c2, __half2 bp, __half2 s,
                                          __half2 H05) {
    __half2 v = __hsub2(ha, e2);
    __half2 n = __hmul2(v, v);
    __half2 P = __hfma2(H05, tanh2(__hfma2(cp, c2, bp)), H05);
    return __hfma2(P, __hsub2(n, s), s);
}
// 3-term weighted sum of gathered half2s
__device__ __forceinline__ __half2 ws3(__half2 w0, __half2 w1, __half2 w2,
                                       unsigned a, unsigned b, unsigned c) {
    return __hfma2(w2, u2h(c), __hfma2(w1, u2h(b), __hmul2(w0, u2h(a))));
}

// ---------------- fused persistent kernel: prep phase + spin barrier + main -
// 444 blocks x 512 threads, 3/SM (co-residency guaranteed: regs<=42 via
// launch_bounds, ~43KB static smem). Prep phase spread over blocks 0..170;
// device-wide epoch barrier (replay-safe, monotonic) separates phases.
// Main unit body identical to the proven round-13 kernel minus one barrier.
__global__ __launch_bounds__(512, 3) void avsl_fused_kernel(
    float* __restrict__ out,
    const float* __restrict__ e1_0, const float* __restrict__ e1_1, const float* __restrict__ e1_2,
    const float* __restrict__ e2_0, const float* __restrict__ e2_1, const float* __restrict__ e2_2,
    const float* __restrict__ c1_1, const float* __restrict__ c1_2,
    const float* __restrict__ c2_1, const float* __restrict__ c2_2,
    const float* __restrict__ a_1,  const float* __restrict__ a_2,
    const float* __restrict__ b_1,  const float* __restrict__ b_2,
    const float* __restrict__ link0, const float* __restrict__ link1)
{
    __shared__ union {
        struct { __half A[D][JT]; __half Bb[D][JT]; } nh;          // 32 KB (main)
        struct { float sm[64][129]; float part[8][64]; float sInv[64]; } tp; // 34.5 KB (prep)
        float4 sRed[16][16];                                        // 4 KB (reduction)
    } u;
    __shared__ uint4    sW[2][D];    // 4 KB
    __shared__ unsigned sIh[5][D];   // 2.5 KB
    __shared__ unsigned sBPh[2][D];  // 1 KB

    const int q   = threadIdx.x;     // 0..7  (j-oct)
    const int g   = threadIdx.y;     // 0..63 (channel pair)
    const int tid = g * 8 + q;
    const int bid = blockIdx.x;

    // ================= PREP PHASE =================
    if (bid < 40) {
        // ---- tiled transpose (e2: with L2-normalization; c2: plain) ----
        const bool isE = bid < 24;
        const int t2 = isE ? bid : bid - 24;
        const int l = t2 >> 3, rt = t2 & 7;
        const float* src = isE ? (l == 0 ? e2_0 : (l == 1 ? e2_1 : e2_2))
                               : (l == 0 ? c2_1 : c2_2);
        const int r0 = rt * 64;
        for (int idx = tid; idx < 64 * 128; idx += 512) {
            int rr = idx >> 7, c = idx & 127;
            u.tp.sm[rr][c] = src[(r0 + rr) * D + c];
        }
        __syncthreads();
        if (isE) {
            int qd = tid >> 6, rr = tid & 63;   // 8 chunks x 16 cols
            float ss = 0.f;
            #pragma unroll 4
            for (int c = qd * 16; c < qd * 16 + 16; ++c) {
                float x = u.tp.sm[rr][c]; ss += x * x;
            }
            u.tp.part[qd][rr] = ss;
            __syncthreads();
            if (tid < 64) {
                float tot = 0.f;
                #pragma unroll
                for (int p = 0; p < 8; ++p) tot += u.tp.part[p][tid];
                u.tp.sInv[tid] = 1.0f / fmaxf(sqrtf(tot), 1e-12f);
            }
        } else {
            if (tid < 64) u.tp.sInv[tid] = 1.0f;
        }
        __syncthreads();
        __half (*dst)[B] = isE ? g_e2nTh[l] : g_c2Th[l];
        for (int idx = tid; idx < 64 * 128; idx += 512) {
            int d2 = idx >> 6, rr = idx & 63;
            dst[d2][r0 + rr] = __float2half_rn(u.tp.sm[rr][d2] * u.tp.sInv[rr]);
        }
    } else if (bid < 136) {
        // ---- e1 normalize: warp per row, 16 rows/block (96 blocks = 1536) --
        int rid = (bid - 40) * 16 + (tid >> 5);   // 0..1535
        int l = rid / 512, r = rid % 512;
        const float* src = (l == 0) ? e1_0 : (l == 1 ? e1_1 : e1_2);
        int lane = tid & 31;
        float4 x = *(const float4*)&src[r * D + lane * 4];
        float ss = x.x * x.x + x.y * x.y + x.z * x.z + x.w * x.w;
        #pragma unroll
        for (int o = 16; o; o >>= 1) ss += __shfl_xor_sync(0xffffffffu, ss, o);
        float inv = 1.0f / fmaxf(sqrtf(ss), 1e-12f);
        float4 v = make_float4(x.x * inv, x.y * inv, x.z * inv, x.w * inv);
        *(float4*)&g_e1n[l][r][lane * 4] = v;
    } else if (bid < 168) {
        // ---- c1p = cert1 * 0.5*alpha: 32 blocks x 4096 = 131072 elems ----
        int base = (bid - 136) * 4096;
        #pragma unroll
        for (int k = 0; k < 8; ++k) {
            int idx = base + k * 512 + tid;       // 0..131071
            int l = idx >> 16;                    // 0..1
            int rem = idx & 65535;
            int d2 = rem & 127;
            const float* c = l ? c1_2 : c1_1;
            const float* a = l ? a_2  : a_1;
            ((float*)g_c1p[l])[rem] = c[rem] * (0.5f * a[d2]);
        }
    } else if (bid == 168) {
        if (tid < 128) {
            g_bp[0][tid] = 0.5f * b_1[tid];
            g_bp[1][tid] = 0.5f * b_2[tid];
        }
    } else if (bid <= 170) {
        // ---- top-3 per column + column normalization ----
        int m = bid - 169;
        if (tid < 128) {
            int e = tid;
            const float* L = m ? link1 : link0;
            float v0 = -1e30f, v1 = -1e30f, v2 = -1e30f;
            int   i0 = 0, i1 = 0, i2 = 0;
            for (int r = 0; r < D; ++r) {
                float w = L[r * D + e];
                if (w > v0)      { v2 = v1; i2 = i1; v1 = v0; i1 = i0; v0 = w; i0 = r; }
                else if (w > v1) { v2 = v1; i2 = i1; v1 = w;  i1 = r; }
                else if (w > v2) { v2 = w;  i2 = r; }
            }
            float inv = 1.0f / (v0 + v1 + v2 + 1e-8f);
            unsigned h0 = (unsigned)__half_as_ushort(__float2half_rn(v0 * inv));
            unsigned h1 = (unsigned)__half_as_ushort(__float2half_rn(v1 * inv));
            unsigned h2 = (unsigned)__half_as_ushort(__float2half_rn(v2 * inv));
            g_wH[m][e] = make_uint4(h0 * 0x10001u, h1 * 0x10001u, h2 * 0x10001u,
                                    (unsigned)i0 | ((unsigned)i1 << 8) | ((unsigned)i2 << 16));
        }
    }
    // (blocks 171..443 have no prep work)

    // ================= DEVICE-WIDE BARRIER (replay-safe epochs) =============
    __syncthreads();
    if (tid == 0) {
        __threadfence();
        unsigned e0 = atomicAdd(&g_release, 0u);
        unsigned old = atomicAdd(&g_arrive, 1u);
        if (old == NBLK - 1) {
            atomicExch(&g_arrive, 0u);
            __threadfence();
            atomicAdd(&g_release, 1u);
        } else {
            while (atomicAdd(&g_release, 0u) == e0) __nanosleep(64);
        }
        __threadfence();
    }
    __syncthreads();

    // ================= MAIN PHASE =================
    // stage W + bp once per block (after barrier: reads prep output)
    if (tid < 2 * D) {
        ((uint4*)sW)[tid] = ((const uint4*)g_wH)[tid];
        ((unsigned*)sBPh)[tid] = h2u(__float2half2_rn(((const float*)g_bp)[tid]));
    }

    // contiguous chunk: first 100 blocks get 10 units, rest 9
    const int base = bid * 9 + (bid < 100 ? bid : 100);
    const int cnt  = 9 + (bid < 100 ? 1 : 0);
    int last_i = -1;

    const __half2 H05 = __float2half2_rn(0.5f);
    const int e0c = g * 2, e1c = g * 2 + 1;

    for (int it = 0; it < cnt; ++it) {
        const int unit = base + it;
        const int i  = unit >> 3;
        const int jj = (unit & 7) * JT + q * 8;

        if (i != last_i) {
            for (int t = tid; t < 5 * D; t += 512) {
                int seg = t >> 7, d = t & 127;
                float v = (seg < 3) ? g_e1n[seg][i][d] : g_c1p[seg - 3][i][d];
                sIh[seg][d] = h2u(__float2half2_rn(v));
            }
            last_i = i;
        }
        __syncthreads();   // (1) staging done + prior-unit sRed reads complete

        // ---- layer 0 -> nh.A ----
        {
            uint4 ea = *(const uint4*)&g_e2nTh[0][e0c][jj];
            uint4 eb = *(const uint4*)&g_e2nTh[0][e1c][jj];
            __half2 h0 = u2h(sIh[0][e0c]), h1 = u2h(sIh[0][e1c]);
            uint4 ra, rb;
            __half2 v;
            v = __hsub2(h0, u2h(ea.x)); ra.x = h2u(__hmul2(v, v));
            v = __hsub2(h0, u2h(ea.y)); ra.y = h2u(__hmul2(v, v));
            v = __hsub2(h0, u2h(ea.z)); ra.z = h2u(__hmul2(v, v));
            v = __hsub2(h0, u2h(ea.w)); ra.w = h2u(__hmul2(v, v));
            v = __hsub2(h1, u2h(eb.x)); rb.x = h2u(__hmul2(v, v));
            v = __hsub2(h1, u2h(eb.y)); rb.y = h2u(__hmul2(v, v));
            v = __hsub2(h1, u2h(eb.z)); rb.z = h2u(__hmul2(v, v));
            v = __hsub2(h1, u2h(eb.w)); rb.w = h2u(__hmul2(v, v));
            *(uint4*)&u.nh.A[e0c][q * 8] = ra;
            *(uint4*)&u.nh.A[e1c][q * 8] = rb;
        }
        __syncthreads();   // (2)

        // ---- layer 1: gather nh.A -> write nh.B ----
        #pragma unroll
        for (int k = 0; k < 2; ++k) {
            const int e = g * 2 + k;
            const uint4 W = sW[0][e];
            const __half2 w0 = u2h(W.x), w1 = u2h(W.y), w2 = u2h(W.z);
            const int o0 = (int)(W.w & 255u) * 8;
            const int o1 = (int)((W.w >> 8) & 255u) * 8;
            const int o2 = (int)((W.w >> 16) & 255u) * 8;
            const uint4* nb = (const uint4*)u.nh.A;
            uint4 r0 = nb[o0 + q], r1 = nb[o1 + q], r2 = nb[o2 + q];
            uint4 e2u = *(const uint4*)&g_e2nTh[1][e][jj];
            uint4 c2u = *(const uint4*)&g_c2Th[0][e][jj];
            __half2 ha = u2h(sIh[1][e]);
            __half2 cp = u2h(sIh[3][e]);
            __half2 bp = u2h(sBPh[0][e]);
            uint4 res;
            res.x = h2u(blend2(ha, u2h(e2u.x), cp, u2h(c2u.x), bp,
                               ws3(w0, w1, w2, r0.x, r1.x, r2.x), H05));
            res.y = h2u(blend2(ha, u2h(e2u.y), cp, u2h(c2u.y), bp,
                               ws3(w0, w1, w2, r0.y, r1.y, r2.y), H05));
            res.z = h2u(blend2(ha, u2h(e2u.z), cp, u2h(c2u.z), bp,
                               ws3(w0, w1, w2, r0.z, r1.z, r2.z), H05));
            res.w = h2u(blend2(ha, u2h(e2u.w), cp, u2h(c2u.w), bp,
                               ws3(w0, w1, w2, r0.w, r1.w, r2.w), H05));
            *(uint4*)&u.nh.Bb[e][q * 8] = res;
        }
        __syncthreads();   // (3)

        // ---- layer 2: gather nh.B + channel accumulation (fp32 acc) ----
        float4 a0 = make_float4(0.f, 0.f, 0.f, 0.f);
        float4 a1 = make_float4(0.f, 0.f, 0.f, 0.f);
        #pragma unroll
        for (int k = 0; k < 2; ++k) {
            const int e = g * 2 + k;
            const uint4 W = sW[1][e];
            const __half2 w0 = u2h(W.x), w1 = u2h(W.y), w2 = u2h(W.z);
            const int o0 = (int)(W.w & 255u) * 8;
            const int o1 = (int)((W.w >> 8) & 255u) * 8;
            const int o2 = (int)((W.w >> 16) & 255u) * 8;
            const uint4* nb = (const uint4*)u.nh.Bb;
            uint4 r0 = nb[o0 + q], r1 = nb[o1 + q], r2 = nb[o2 + q];
            uint4 e2u = *(const uint4*)&g_e2nTh[2][e][jj];
            uint4 c2u = *(const uint4*)&g_c2Th[1][e][jj];
            __half2 ha = u2h(sIh[2][e]);
            __half2 cp = u2h(sIh[4][e]);
            __half2 bp = u2h(sBPh[1][e]);
            __half2 rA = blend2(ha, u2h(e2u.x), cp, u2h(c2u.x), bp,
                                ws3(w0, w1, w2, r0.x, r1.x, r2.x), H05);
            __half2 rB = blend2(ha, u2h(e2u.y), cp, u2h(c2u.y), bp,
                                ws3(w0, w1, w2, r0.y, r1.y, r2.y), H05);
            __half2 rC = blend2(ha, u2h(e2u.z), cp, u2h(c2u.z), bp,
                                ws3(w0, w1, w2, r0.z, r1.z, r2.z), H05);
            __half2 rD = blend2(ha, u2h(e2u.w), cp, u2h(c2u.w), bp,
                                ws3(w0, w1, w2, r0.w, r1.w, r2.w), H05);
            float2 fA = __half22float2(rA), fB = __half22float2(rB);
            float2 fC = __half22float2(rC), fD = __half22float2(rD);
            a0.x += fA.x; a0.y += fA.y; a0.z += fB.x; a0.w += fB.y;
            a1.x += fC.x; a1.y += fC.y; a1.z += fD.x; a1.w += fD.y;
        }

        // fold the 4 channel-pair groups sharing a warp (8-lane groups)
        a0.x += __shfl_down_sync(0xffffffffu, a0.x, 16);
        a0.y += __shfl_down_sync(0xffffffffu, a0.y, 16);
        a0.z += __shfl_down_sync(0xffffffffu, a0.z, 16);
        a0.w += __shfl_down_sync(0xffffffffu, a0.w, 16);
        a1.x += __shfl_down_sync(0xffffffffu, a1.x, 16);
        a1.y += __shfl_down_sync(0xffffffffu, a1.y, 16);
        a1.z += __shfl_down_sync(0xffffffffu, a1.z, 16);
        a1.w += __shfl_down_sync(0xffffffffu, a1.w, 16);
        a0.x += __shfl_down_sync(0xffffffffu, a0.x, 8);
        a0.y += __shfl_down_sync(0xffffffffu, a0.y, 8);
        a0.z += __shfl_down_sync(0xffffffffu, a0.z, 8);
        a0.w += __shfl_down_sync(0xffffffffu, a0.w, 8);
        a1.x += __shfl_down_sync(0xffffffffu, a1.x, 8);
        a1.y += __shfl_down_sync(0xffffffffu, a1.y, 8);
        a1.z += __shfl_down_sync(0xffffffffu, a1.z, 8);
        a1.w += __shfl_down_sync(0xffffffffu, a1.w, 8);
        // NOTE: no barrier needed here — sRed aliases nh.A (last read before
        // barrier (3)); layer-2 only touches nh.B, so writes can't race.
        const int w = tid >> 5, lane = tid & 31;
        if (lane < 8) {
            u.sRed[w][lane * 2]     = a0;
            u.sRed[w][lane * 2 + 1] = a1;
        }
        __syncthreads();   // (4) sRed writes visible
        if (tid < 16) {
            float4 tot = make_float4(0.f, 0.f, 0.f, 0.f);
            #pragma unroll
            for (int ww = 0; ww < 16; ++ww) {
                float4 t = u.sRed[ww][tid];
                tot.x += t.x; tot.y += t.y; tot.z += t.z; tot.w += t.w;
            }
            *(float4*)&out[i * B + (unit & 7) * JT + tid * 4] = tot;
        }
    }
}

// ---------------- launch ----------------
extern "C" void kernel_launch(void* const* d_in, const int* in_sizes, int n_in,
                              void* d_out, int out_size)
{
    (void)n_in; (void)out_size;

    const float *e1_0, *e1_1, *e1_2, *e2_0, *e2_1, *e2_2;
    const float *c1_1, *c1_2, *c2_1, *c2_2;
    const float *a_1, *a_2, *b_1, *b_2;
    const float *link0, *link1;

    // Detect input ordering at runtime via element counts (see round-1 note).
    if (in_sizes[4] == 128) {
        // dict insertion order (interleaved per layer)
        e1_0 = (const float*)d_in[0];   e2_0 = (const float*)d_in[1];
        e1_1 = (const float*)d_in[6];   e2_1 = (const float*)d_in[7];
        e1_2 = (const float*)d_in[12];  e2_2 = (const float*)d_in[13];
        c1_1 = (const float*)d_in[8];   c2_1 = (const float*)d_in[9];
        c1_2 = (const float*)d_in[14];  c2_2 = (const float*)d_in[15];
        a_1  = (const float*)d_in[10];  b_1  = (const float*)d_in[11];
        a_2  = (const float*)d_in[16];  b_2  = (const float*)d_in[17];
        link0 = (const float*)d_in[18]; link1 = (const float*)d_in[19];
    } else {
        // function-signature order (grouped)
        e1_0 = (const float*)d_in[0];   e1_1 = (const float*)d_in[1];
        e1_2 = (const float*)d_in[2];
        e2_0 = (const float*)d_in[3];   e2_1 = (const float*)d_in[4];
        e2_2 = (const float*)d_in[5];
        c1_1 = (const float*)d_in[7];   c1_2 = (const float*)d_in[8];
        c2_1 = (const float*)d_in[10];  c2_2 = (const float*)d_in[11];
        a_1  = (const float*)d_in[13];  a_2  = (const float*)d_in[14];
        b_1  = (const float*)d_in[16];  b_2  = (const float*)d_in[17];
        link0 = (const float*)d_in[18]; link1 = (const float*)d_in[19];
    }

    dim3 blk(8, 64);
    avsl_fused_kernel<<<NBLK, blk>>>((float*)d_out,
                                     e1_0, e1_1, e1_2, e2_0, e2_1, e2_2,
                                     c1_1, c1_2, c2_1, c2_2, a_1, a_2,
                                     b_1, b_2, link0, link1);
}

// round 16
// speedup vs baseline: 1.0043x; 1.0043x over previous
#include <cuda_runtime.h>
#include <cuda_fp16.h>

#define B 512
#define D 128
#define JT 64            // j per work unit
#define NBLK 444         // persistent grid: 148 SMs x 3 blocks

// ---------------- device scratch (no allocation allowed) ----------------
__device__ float  g_e1n[3][B][D];     // normalized emb1, row-major [l][i][d]
__device__ __half g_e2nTh[3][D][B];   // normalized emb2, fp16, transposed [l][d][j]
__device__ float  g_c1p[2][B][D];     // cert1_{1,2} * 0.5*alpha_{1,2}
__device__ __half g_c2Th[2][D][B];    // cert2_{1,2}, fp16, transposed [l][d][j]
__device__ float  g_bp[2][D];         // 0.5*beta_{1,2}
__device__ uint4  g_wH[2][D];         // .x/.y/.z = broadcast half2 of w0..w2, .w = packed idx

__device__ __forceinline__ __half2 u2h(unsigned x) {
    __half2 h; *(unsigned*)&h = x; return h;
}
__device__ __forceinline__ unsigned h2u(__half2 h) {
    return *(unsigned*)&h;
}
__device__ __forceinline__ __half2 tanh2(__half2 x) {
    unsigned xi = h2u(x), yo;
    asm("tanh.approx.f16x2 %0, %1;" : "=r"(yo) : "r"(xi));
    return u2h(yo);
}
// r = s + P*(n-s),  n = (a-e2)^2,  P = 0.5*tanh(cp*c2+bp)+0.5   (all half2)
__device__ __forceinline__ __half2 blend2(__half2 ha, __half2 e2, __half2 cp,
                                          __half2 c2, __half2 bp, __half2 s,
                                          __half2 H05) {
    __half2 v = __hsub2(ha, e2);
    __half2 n = __hmul2(v, v);
    __half2 P = __hfma2(H05, tanh2(__hfma2(cp, c2, bp)), H05);
    return __hfma2(P, __hsub2(n, s), s);
}
// 3-term weighted sum of gathered half2s
__device__ __forceinline__ __half2 ws3(__half2 w0, __half2 w1, __half2 w2,
                                       unsigned a, unsigned b, unsigned c) {
    return __hfma2(w2, u2h(c), __hfma2(w1, u2h(b), __hmul2(w0, u2h(a))));
}

// ---------------- prep v2 (round-13, proven) ----------------
__global__ __launch_bounds__(256) void prep_kernel(
    const float* __restrict__ e1_0, const float* __restrict__ e1_1, const float* __restrict__ e1_2,
    const float* __restrict__ e2_0, const float* __restrict__ e2_1, const float* __restrict__ e2_2,
    const float* __restrict__ c1_1, const float* __restrict__ c1_2,
    const float* __restrict__ c2_1, const float* __restrict__ c2_2,
    const float* __restrict__ a_1,  const float* __restrict__ a_2,
    const float* __restrict__ b_1,  const float* __restrict__ b_2,
    const float* __restrict__ link0, const float* __restrict__ link1)
{
    __shared__ float sm[64][129];
    __shared__ float part[4][64];
    __shared__ float sInv[64];

    const int bid = blockIdx.x;
    const int t   = threadIdx.x;

    if (bid < 40) {
        const bool isE = bid < 24;
        const int t2 = isE ? bid : bid - 24;
        const int l = t2 >> 3, rt = t2 & 7;
        const float* src = isE ? (l == 0 ? e2_0 : (l == 1 ? e2_1 : e2_2))
                               : (l == 0 ? c2_1 : c2_2);
        const int r0 = rt * 64;
        for (int idx = t; idx < 64 * 128; idx += 256) {
            int rr = idx >> 7, c = idx & 127;
            sm[rr][c] = src[(r0 + rr) * D + c];
        }
        __syncthreads();
        if (isE) {
            int qd = t >> 6, rr = t & 63;
            float ss = 0.f;
            #pragma unroll 8
            for (int c = qd * 32; c < qd * 32 + 32; ++c) {
                float x = sm[rr][c]; ss += x * x;
            }
            part[qd][rr] = ss;
            __syncthreads();
            if (t < 64) {
                float tot = part[0][t] + part[1][t] + part[2][t] + part[3][t];
                sInv[t] = 1.0f / fmaxf(sqrtf(tot), 1e-12f);
            }
        } else {
            if (t < 64) sInv[t] = 1.0f;
        }
        __syncthreads();
        __half (*dst)[B] = isE ? g_e2nTh[l] : g_c2Th[l];
        for (int idx = t; idx < 64 * 128; idx += 256) {
            int d2 = idx >> 6, rr = idx & 63;
            dst[d2][r0 + rr] = __float2half_rn(sm[rr][d2] * sInv[rr]);
        }
    } else if (bid < 232) {
        int rid = (bid - 40) * 8 + (t >> 5);
        int l = rid / 512, r = rid % 512;
        const float* src = (l == 0) ? e1_0 : (l == 1 ? e1_1 : e1_2);
        int lane = t & 31;
        float4 x = *(const float4*)&src[r * D + lane * 4];
        float ss = x.x * x.x + x.y * x.y + x.z * x.z + x.w * x.w;
        #pragma unroll
        for (int o = 16; o; o >>= 1) ss += __shfl_xor_sync(0xffffffffu, ss, o);
        float inv = 1.0f / fmaxf(sqrtf(ss), 1e-12f);
        float4 v = make_float4(x.x * inv, x.y * inv, x.z * inv, x.w * inv);
        *(float4*)&g_e1n[l][r][lane * 4] = v;
    } else if (bid < 296) {
        int base = (bid - 232) * 2048;
        #pragma unroll
        for (int k = 0; k < 8; ++k) {
            int idx = base + k * 256 + t;
            int l = idx >> 16;
            int rem = idx & 65535;
            int d2 = rem & 127;
            const float* c = l ? c1_2 : c1_1;
            const float* a = l ? a_2  : a_1;
            ((float*)g_c1p[l])[rem] = c[rem] * (0.5f * a[d2]);
        }
    } else if (bid == 296) {
        if (t < 128) {
            g_bp[0][t] = 0.5f * b_1[t];
            g_bp[1][t] = 0.5f * b_2[t];
        }
    } else {
        int m = bid - 297;
        if (t < 128) {
            int e = t;
            const float* L = m ? link1 : link0;
            float v0 = -1e30f, v1 = -1e30f, v2 = -1e30f;
            int   i0 = 0, i1 = 0, i2 = 0;
            for (int r = 0; r < D; ++r) {
                float w = L[r * D + e];
                if (w > v0)      { v2 = v1; i2 = i1; v1 = v0; i1 = i0; v0 = w; i0 = r; }
                else if (w > v1) { v2 = v1; i2 = i1; v1 = w;  i1 = r; }
                else if (w > v2) { v2 = w;  i2 = r; }
            }
            float inv = 1.0f / (v0 + v1 + v2 + 1e-8f);
            unsigned h0 = (unsigned)__half_as_ushort(__float2half_rn(v0 * inv));
            unsigned h1 = (unsigned)__half_as_ushort(__float2half_rn(v1 * inv));
            unsigned h2 = (unsigned)__half_as_ushort(__float2half_rn(v2 * inv));
            g_wH[m][e] = make_uint4(h0 * 0x10001u, h1 * 0x10001u, h2 * 0x10001u,
                                    (unsigned)i0 | ((unsigned)i1 << 8) | ((unsigned)i2 << 16));
        }
    }
}

// ---------------- fused similarity kernel (persistent, 4 barriers/unit) -----
// 444 persistent blocks (3/SM), each a contiguous chunk of 9-10 (i, j-tile)
// units. Round-13 body with: (a) barrier (4) removed — sRed aliases nh.A whose
// last read precedes barrier (3), layer-2 touches only nh.B (validated in
// round 15); (b) layer-2 accumulation kept in half2 (validated round 11).
__global__ __launch_bounds__(512, 3) void avsl_main_kernel(float* __restrict__ out)
{
    __shared__ union {
        struct { __half A[D][JT]; __half Bb[D][JT]; } nh;  // 32 KB
        float4 sRed[16][16];     // 4 KB, aliased over nh.A (dead at reduction)
    } u;
    __shared__ uint4    sW[2][D];    // 4 KB
    __shared__ unsigned sIh[5][D];   // 2.5 KB
    __shared__ unsigned sBPh[2][D];  // 1 KB

    const int q   = threadIdx.x;     // 0..7  (j-oct)
    const int g   = threadIdx.y;     // 0..63 (channel pair)
    const int tid = g * 8 + q;
    const int bid = blockIdx.x;

    // stage W + bp once per persistent block
    if (tid < 2 * D) {
        ((uint4*)sW)[tid] = ((const uint4*)g_wH)[tid];
        ((unsigned*)sBPh)[tid] = h2u(__float2half2_rn(((const float*)g_bp)[tid]));
    }

    // contiguous chunk: first 100 blocks get 10 units, rest 9
    const int base = bid * 9 + (bid < 100 ? bid : 100);
    const int cnt  = 9 + (bid < 100 ? 1 : 0);
    int last_i = -1;

    const __half2 H05 = __float2half2_rn(0.5f);
    const int e0 = g * 2, e1c = g * 2 + 1;

    for (int it = 0; it < cnt; ++it) {
        const int unit = base + it;
        const int i  = unit >> 3;
        const int jj = (unit & 7) * JT + q * 8;

        if (i != last_i) {
            for (int t = tid; t < 5 * D; t += 512) {
                int seg = t >> 7, d = t & 127;
                float v = (seg < 3) ? g_e1n[seg][i][d] : g_c1p[seg - 3][i][d];
                sIh[seg][d] = h2u(__float2half2_rn(v));
            }
            last_i = i;
        }
        __syncthreads();   // (1) staging done + prior-unit sRed reads complete

        // ---- layer 0 -> nh.A ----
        {
            uint4 ea = *(const uint4*)&g_e2nTh[0][e0][jj];
            uint4 eb = *(const uint4*)&g_e2nTh[0][e1c][jj];
            __half2 h0 = u2h(sIh[0][e0]), h1 = u2h(sIh[0][e1c]);
            uint4 ra, rb;
            __half2 v;
            v = __hsub2(h0, u2h(ea.x)); ra.x = h2u(__hmul2(v, v));
            v = __hsub2(h0, u2h(ea.y)); ra.y = h2u(__hmul2(v, v));
            v = __hsub2(h0, u2h(ea.z)); ra.z = h2u(__hmul2(v, v));
            v = __hsub2(h0, u2h(ea.w)); ra.w = h2u(__hmul2(v, v));
            v = __hsub2(h1, u2h(eb.x)); rb.x = h2u(__hmul2(v, v));
            v = __hsub2(h1, u2h(eb.y)); rb.y = h2u(__hmul2(v, v));
            v = __hsub2(h1, u2h(eb.z)); rb.z = h2u(__hmul2(v, v));
            v = __hsub2(h1, u2h(eb.w)); rb.w = h2u(__hmul2(v, v));
            *(uint4*)&u.nh.A[e0][q * 8]  = ra;
            *(uint4*)&u.nh.A[e1c][q * 8] = rb;
        }
        __syncthreads();   // (2)

        // ---- layer 1: gather nh.A -> write nh.B ----
        #pragma unroll
        for (int k = 0; k < 2; ++k) {
            const int e = g * 2 + k;
            const uint4 W = sW[0][e];
            const __half2 w0 = u2h(W.x), w1 = u2h(W.y), w2 = u2h(W.z);
            const int o0 = (int)(W.w & 255u) * 8;
            const int o1 = (int)((W.w >> 8) & 255u) * 8;
            const int o2 = (int)((W.w >> 16) & 255u) * 8;
            const uint4* nb = (const uint4*)u.nh.A;
            uint4 r0 = nb[o0 + q], r1 = nb[o1 + q], r2 = nb[o2 + q];
            uint4 e2u = *(const uint4*)&g_e2nTh[1][e][jj];
            uint4 c2u = *(const uint4*)&g_c2Th[0][e][jj];
            __half2 ha = u2h(sIh[1][e]);
            __half2 cp = u2h(sIh[3][e]);
            __half2 bp = u2h(sBPh[0][e]);
            uint4 res;
            res.x = h2u(blend2(ha, u2h(e2u.x), cp, u2h(c2u.x), bp,
                               ws3(w0, w1, w2, r0.x, r1.x, r2.x), H05));
            res.y = h2u(blend2(ha, u2h(e2u.y), cp, u2h(c2u.y), bp,
                               ws3(w0, w1, w2, r0.y, r1.y, r2.y), H05));
            res.z = h2u(blend2(ha, u2h(e2u.z), cp, u2h(c2u.z), bp,
                               ws3(w0, w1, w2, r0.z, r1.z, r2.z), H05));
            res.w = h2u(blend2(ha, u2h(e2u.w), cp, u2h(c2u.w), bp,
                               ws3(w0, w1, w2, r0.w, r1.w, r2.w), H05));
            *(uint4*)&u.nh.Bb[e][q * 8] = res;
        }
        __syncthreads();   // (3)

        // ---- layer 2: gather nh.B + half2 channel accumulation ----
        __half2 acc0 = u2h(0u), acc1 = u2h(0u), acc2 = u2h(0u), acc3 = u2h(0u);
        #pragma unroll
        for (int k = 0; k < 2; ++k) {
            const int e = g * 2 + k;
            const uint4 W = sW[1][e];
            const __half2 w0 = u2h(W.x), w1 = u2h(W.y), w2 = u2h(W.z);
            const int o0 = (int)(W.w & 255u) * 8;
            const int o1 = (int)((W.w >> 8) & 255u) * 8;
            const int o2 = (int)((W.w >> 16) & 255u) * 8;
            const uint4* nb = (const uint4*)u.nh.Bb;
            uint4 r0 = nb[o0 + q], r1 = nb[o1 + q], r2 = nb[o2 + q];
            uint4 e2u = *(const uint4*)&g_e2nTh[2][e][jj];
            uint4 c2u = *(const uint4*)&g_c2Th[1][e][jj];
            __half2 ha = u2h(sIh[2][e]);
            __half2 cp = u2h(sIh[4][e]);
            __half2 bp = u2h(sBPh[1][e]);
            acc0 = __hadd2(acc0, blend2(ha, u2h(e2u.x), cp, u2h(c2u.x), bp,
                                        ws3(w0, w1, w2, r0.x, r1.x, r2.x), H05));
            acc1 = __hadd2(acc1, blend2(ha, u2h(e2u.y), cp, u2h(c2u.y), bp,
                                        ws3(w0, w1, w2, r0.y, r1.y, r2.y), H05));
            acc2 = __hadd2(acc2, blend2(ha, u2h(e2u.z), cp, u2h(c2u.z), bp,
                                        ws3(w0, w1, w2, r0.z, r1.z, r2.z), H05));
            acc3 = __hadd2(acc3, blend2(ha, u2h(e2u.w), cp, u2h(c2u.w), bp,
                                        ws3(w0, w1, w2, r0.w, r1.w, r2.w), H05));
        }
        // convert once to fp32
        float2 f0 = __half22float2(acc0), f1 = __half22float2(acc1);
        float2 f2 = __half22float2(acc2), f3 = __half22float2(acc3);
        float4 a0 = make_float4(f0.x, f0.y, f1.x, f1.y);
        float4 a1 = make_float4(f2.x, f2.y, f3.x, f3.y);

        // fold the 4 channel-pair groups sharing a warp (8-lane groups)
        a0.x += __shfl_down_sync(0xffffffffu, a0.x, 16);
        a0.y += __shfl_down_sync(0xffffffffu, a0.y, 16);
        a0.z += __shfl_down_sync(0xffffffffu, a0.z, 16);
        a0.w += __shfl_down_sync(0xffffffffu, a0.w, 16);
        a1.x += __shfl_down_sync(0xffffffffu, a1.x, 16);
        a1.y += __shfl_down_sync(0xffffffffu, a1.y, 16);
        a1.z += __shfl_down_sync(0xffffffffu, a1.z, 16);
        a1.w += __shfl_down_sync(0xffffffffu, a1.w, 16);
        a0.x += __shfl_down_sync(0xffffffffu, a0.x, 8);
        a0.y += __shfl_down_sync(0xffffffffu, a0.y, 8);
        a0.z += __shfl_down_sync(0xffffffffu, a0.z, 8);
        a0.w += __shfl_down_sync(0xffffffffu, a0.w, 8);
        a1.x += __shfl_down_sync(0xffffffffu, a1.x, 8);
        a1.y += __shfl_down_sync(0xffffffffu, a1.y, 8);
        a1.z += __shfl_down_sync(0xffffffffu, a1.z, 8);
        a1.w += __shfl_down_sync(0xffffffffu, a1.w, 8);
        // no barrier needed: sRed aliases nh.A (last read before barrier (3));
        // layer-2 only reads nh.B (validated in round 15's fused kernel)
        const int w = tid >> 5, lane = tid & 31;
        if (lane < 8) {
            u.sRed[w][lane * 2]     = a0;
            u.sRed[w][lane * 2 + 1] = a1;
        }
        __syncthreads();   // (4) sRed writes visible
        if (tid < 16) {
            float4 tot = make_float4(0.f, 0.f, 0.f, 0.f);
            #pragma unroll
            for (int ww = 0; ww < 16; ++ww) {
                float4 t = u.sRed[ww][tid];
                tot.x += t.x; tot.y += t.y; tot.z += t.z; tot.w += t.w;
            }
            *(float4*)&out[i * B + (unit & 7) * JT + tid * 4] = tot;
        }
    }
}

// ---------------- launch ----------------
extern "C" void kernel_launch(void* const* d_in, const int* in_sizes, int n_in,
                              void* d_out, int out_size)
{
    (void)n_in; (void)out_size;

    const float *e1_0, *e1_1, *e1_2, *e2_0, *e2_1, *e2_2;
    const float *c1_1, *c1_2, *c2_1, *c2_2;
    const float *a_1, *a_2, *b_1, *b_2;
    const float *link0, *link1;

    // Detect input ordering at runtime via element counts (see round-1 note).
    if (in_sizes[4] == 128) {
        // dict insertion order (interleaved per layer)
        e1_0 = (const float*)d_in[0];   e2_0 = (const float*)d_in[1];
        e1_1 = (const float*)d_in[6];   e2_1 = (const float*)d_in[7];
        e1_2 = (const float*)d_in[12];  e2_2 = (const float*)d_in[13];
        c1_1 = (const float*)d_in[8];   c2_1 = (const float*)d_in[9];
        c1_2 = (const float*)d_in[14];  c2_2 = (const float*)d_in[15];
        a_1  = (const float*)d_in[10];  b_1  = (const float*)d_in[11];
        a_2  = (const float*)d_in[16];  b_2  = (const float*)d_in[17];
        link0 = (const float*)d_in[18]; link1 = (const float*)d_in[19];
    } else {
        // function-signature order (grouped)
        e1_0 = (const float*)d_in[0];   e1_1 = (const float*)d_in[1];
        e1_2 = (const float*)d_in[2];
        e2_0 = (const float*)d_in[3];   e2_1 = (const float*)d_in[4];
        e2_2 = (const float*)d_in[5];
        c1_1 = (const float*)d_in[7];   c1_2 = (const float*)d_in[8];
        c2_1 = (const float*)d_in[10];  c2_2 = (const float*)d_in[11];
        a_1  = (const float*)d_in[13];  a_2  = (const float*)d_in[14];
        b_1  = (const float*)d_in[16];  b_2  = (const float*)d_in[17];
        link0 = (const float*)d_in[18]; link1 = (const float*)d_in[19];
    }

    prep_kernel<<<299, 256>>>(e1_0, e1_1, e1_2, e2_0, e2_1, e2_2,
                              c1_1, c1_2, c2_1, c2_2, a_1, a_2, b_1, b_2,
                              link0, link1);

    dim3 blk(8, 64);
    avsl_main_kernel<<<NBLK, blk>>>((float*)d_out);
}

// round 17
// speedup vs baseline: 1.0310x; 1.0266x over previous
#include <cuda_runtime.h>
#include <cuda_fp16.h>

#define B 512
#define D 128
#define JT 64            // j per work unit
#define NBLK 444         // persistent grid: 148 SMs x 3 blocks

// ---------------- device scratch (no allocation allowed) ----------------
__device__ float  g_e1n[3][B][D];     // normalized emb1, row-major [l][i][d]
__device__ __half g_e2nTh[3][D][B];   // normalized emb2, fp16, transposed [l][d][j]
__device__ float  g_c1p[2][B][D];     // cert1_{1,2} * 0.5*alpha_{1,2}
__device__ __half g_c2Th[2][D][B];    // cert2_{1,2}, fp16, transposed [l][d][j]
__device__ float  g_bp[2][D];         // 0.5*beta_{1,2}
__device__ uint4  g_wH[2][D];         // .x/.y/.z = broadcast half2 of w0..w2, .w = packed idx

__device__ __forceinline__ __half2 u2h(unsigned x) {
    __half2 h; *(unsigned*)&h = x; return h;
}
__device__ __forceinline__ unsigned h2u(__half2 h) {
    return *(unsigned*)&h;
}
__device__ __forceinline__ __half2 tanh2(__half2 x) {
    unsigned xi = h2u(x), yo;
    asm("tanh.approx.f16x2 %0, %1;" : "=r"(yo) : "r"(xi));
    return u2h(yo);
}
// r = s + P*(n-s),  n = (a-e2)^2,  P = 0.5*tanh(cp*c2+bp)+0.5   (all half2)
__device__ __forceinline__ __half2 blend2(__half2 ha, __half2 e2, __half2 cp,
                                          __half2 c2, __half2 bp, __half2 s,
                                          __half2 H05) {
    __half2 v = __hsub2(ha, e2);
    __half2 n = __hmul2(v, v);
    __half2 P = __hfma2(H05, tanh2(__hfma2(cp, c2, bp)), H05);
    return __hfma2(P, __hsub2(n, s), s);
}
// 3-term weighted sum of gathered half2s
__device__ __forceinline__ __half2 ws3(__half2 w0, __half2 w1, __half2 w2,
                                       unsigned a, unsigned b, unsigned c) {
    return __hfma2(w2, u2h(c), __hfma2(w1, u2h(b), __hmul2(w0, u2h(a))));
}

// ---------------- prep v2 (round-13, proven) ----------------
__global__ __launch_bounds__(256) void prep_kernel(
    const float* __restrict__ e1_0, const float* __restrict__ e1_1, const float* __restrict__ e1_2,
    const float* __restrict__ e2_0, const float* __restrict__ e2_1, const float* __restrict__ e2_2,
    const float* __restrict__ c1_1, const float* __restrict__ c1_2,
    const float* __restrict__ c2_1, const float* __restrict__ c2_2,
    const float* __restrict__ a_1,  const float* __restrict__ a_2,
    const float* __restrict__ b_1,  const float* __restrict__ b_2,
    const float* __restrict__ link0, const float* __restrict__ link1)
{
    __shared__ float sm[64][129];
    __shared__ float part[4][64];
    __shared__ float sInv[64];

    const int bid = blockIdx.x;
    const int t   = threadIdx.x;

    if (bid < 40) {
        const bool isE = bid < 24;
        const int t2 = isE ? bid : bid - 24;
        const int l = t2 >> 3, rt = t2 & 7;
        const float* src = isE ? (l == 0 ? e2_0 : (l == 1 ? e2_1 : e2_2))
                               : (l == 0 ? c2_1 : c2_2);
        const int r0 = rt * 64;
        for (int idx = t; idx < 64 * 128; idx += 256) {
            int rr = idx >> 7, c = idx & 127;
            sm[rr][c] = src[(r0 + rr) * D + c];
        }
        __syncthreads();
        if (isE) {
            int qd = t >> 6, rr = t & 63;
            float ss = 0.f;
            #pragma unroll 8
            for (int c = qd * 32; c < qd * 32 + 32; ++c) {
                float x = sm[rr][c]; ss += x * x;
            }
            part[qd][rr] = ss;
            __syncthreads();
            if (t < 64) {
                float tot = part[0][t] + part[1][t] + part[2][t] + part[3][t];
                sInv[t] = 1.0f / fmaxf(sqrtf(tot), 1e-12f);
            }
        } else {
            if (t < 64) sInv[t] = 1.0f;
        }
        __syncthreads();
        __half (*dst)[B] = isE ? g_e2nTh[l] : g_c2Th[l];
        for (int idx = t; idx < 64 * 128; idx += 256) {
            int d2 = idx >> 6, rr = idx & 63;
            dst[d2][r0 + rr] = __float2half_rn(sm[rr][d2] * sInv[rr]);
        }
    } else if (bid < 232) {
        int rid = (bid - 40) * 8 + (t >> 5);
        int l = rid / 512, r = rid % 512;
        const float* src = (l == 0) ? e1_0 : (l == 1 ? e1_1 : e1_2);
        int lane = t & 31;
        float4 x = *(const float4*)&src[r * D + lane * 4];
        float ss = x.x * x.x + x.y * x.y + x.z * x.z + x.w * x.w;
        #pragma unroll
        for (int o = 16; o; o >>= 1) ss += __shfl_xor_sync(0xffffffffu, ss, o);
        float inv = 1.0f / fmaxf(sqrtf(ss), 1e-12f);
        float4 v = make_float4(x.x * inv, x.y * inv, x.z * inv, x.w * inv);
        *(float4*)&g_e1n[l][r][lane * 4] = v;
    } else if (bid < 296) {
        int base = (bid - 232) * 2048;
        #pragma unroll
        for (int k = 0; k < 8; ++k) {
            int idx = base + k * 256 + t;
            int l = idx >> 16;
            int rem = idx & 65535;
            int d2 = rem & 127;
            const float* c = l ? c1_2 : c1_1;
            const float* a = l ? a_2  : a_1;
            ((float*)g_c1p[l])[rem] = c[rem] * (0.5f * a[d2]);
        }
    } else if (bid == 296) {
        if (t < 128) {
            g_bp[0][t] = 0.5f * b_1[t];
            g_bp[1][t] = 0.5f * b_2[t];
        }
    } else {
        int m = bid - 297;
        if (t < 128) {
            int e = t;
            const float* L = m ? link1 : link0;
            float v0 = -1e30f, v1 = -1e30f, v2 = -1e30f;
            int   i0 = 0, i1 = 0, i2 = 0;
            for (int r = 0; r < D; ++r) {
                float w = L[r * D + e];
                if (w > v0)      { v2 = v1; i2 = i1; v1 = v0; i1 = i0; v0 = w; i0 = r; }
                else if (w > v1) { v2 = v1; i2 = i1; v1 = w;  i1 = r; }
                else if (w > v2) { v2 = w;  i2 = r; }
            }
            float inv = 1.0f / (v0 + v1 + v2 + 1e-8f);
            unsigned h0 = (unsigned)__half_as_ushort(__float2half_rn(v0 * inv));
            unsigned h1 = (unsigned)__half_as_ushort(__float2half_rn(v1 * inv));
            unsigned h2 = (unsigned)__half_as_ushort(__float2half_rn(v2 * inv));
            g_wH[m][e] = make_uint4(h0 * 0x10001u, h1 * 0x10001u, h2 * 0x10001u,
                                    (unsigned)i0 | ((unsigned)i1 << 8) | ((unsigned)i2 << 16));
        }
    }
}

// ---------------- fused similarity kernel (persistent, 3 barriers/unit) -----
// 444 persistent blocks (3/SM), contiguous chunks of 9-10 (i, j-tile) units.
// Round-13 body (fp32 acc) with sRed in its OWN buffer (no nh alias):
//   bar(1) only when sIh restaged; bar(2) A-ready; bar(3) B-ready (also
//   separates prior tail's sRed reads from this unit's sRed writes);
//   bar(4) sRed-ready. All producer->consumer pairs barrier-separated.
__global__ __launch_bounds__(512, 3) void avsl_main_kernel(float* __restrict__ out)
{
    __shared__ __half   nhA[D][JT];   // 16 KB
    __shared__ __half   nhB[D][JT];   // 16 KB
    __shared__ float4   sRed[16][16]; // 4 KB (disjoint from nh)
    __shared__ uint4    sW[2][D];     // 4 KB
    __shared__ unsigned sIh[5][D];    // 2.5 KB
    __shared__ unsigned sBPh[2][D];   // 1 KB

    const int q   = threadIdx.x;     // 0..7  (j-oct)
    const int g   = threadIdx.y;     // 0..63 (channel pair)
    const int tid = g * 8 + q;
    const int bid = blockIdx.x;

    // stage W + bp once per persistent block
    if (tid < 2 * D) {
        ((uint4*)sW)[tid] = ((const uint4*)g_wH)[tid];
        ((unsigned*)sBPh)[tid] = h2u(__float2half2_rn(((const float*)g_bp)[tid]));
    }

    // contiguous chunk: first 100 blocks get 10 units, rest 9
    const int base = bid * 9 + (bid < 100 ? bid : 100);
    const int cnt  = 9 + (bid < 100 ? 1 : 0);
    int last_i = -1;

    const __half2 H05 = __float2half2_rn(0.5f);
    const int e0 = g * 2, e1c = g * 2 + 1;

    for (int it = 0; it < cnt; ++it) {
        const int unit = base + it;
        const int i  = unit >> 3;
        const int jj = (unit & 7) * JT + q * 8;

        if (i != last_i) {
            for (int t = tid; t < 5 * D; t += 512) {
                int seg = t >> 7, d = t & 127;
                float v = (seg < 3) ? g_e1n[seg][i][d] : g_c1p[seg - 3][i][d];
                sIh[seg][d] = h2u(__float2half2_rn(v));
            }
            last_i = i;
            __syncthreads();   // (1) staging visible (uniform branch; also
                               // covers first-iteration sW/sBPh staging)
        }

        // ---- layer 0 -> nhA ----
        {
            uint4 ea = *(const uint4*)&g_e2nTh[0][e0][jj];
            uint4 eb = *(const uint4*)&g_e2nTh[0][e1c][jj];
            __half2 h0 = u2h(sIh[0][e0]), h1 = u2h(sIh[0][e1c]);
            uint4 ra, rb;
            __half2 v;
            v = __hsub2(h0, u2h(ea.x)); ra.x = h2u(__hmul2(v, v));
            v = __hsub2(h0, u2h(ea.y)); ra.y = h2u(__hmul2(v, v));
            v = __hsub2(h0, u2h(ea.z)); ra.z = h2u(__hmul2(v, v));
            v = __hsub2(h0, u2h(ea.w)); ra.w = h2u(__hmul2(v, v));
            v = __hsub2(h1, u2h(eb.x)); rb.x = h2u(__hmul2(v, v));
            v = __hsub2(h1, u2h(eb.y)); rb.y = h2u(__hmul2(v, v));
            v = __hsub2(h1, u2h(eb.z)); rb.z = h2u(__hmul2(v, v));
            v = __hsub2(h1, u2h(eb.w)); rb.w = h2u(__hmul2(v, v));
            *(uint4*)&nhA[e0][q * 8]  = ra;
            *(uint4*)&nhA[e1c][q * 8] = rb;
        }
        __syncthreads();   // (2) nhA ready (prior readers of nhA done at (2) of
                           //     previous iteration; writes WAR-safe via (3),(4))

        // ---- layer 1: gather nhA -> write nhB ----
        #pragma unroll
        for (int k = 0; k < 2; ++k) {
            const int e = g * 2 + k;
            const uint4 W = sW[0][e];
            const __half2 w0 = u2h(W.x), w1 = u2h(W.y), w2 = u2h(W.z);
            const int o0 = (int)(W.w & 255u) * 8;
            const int o1 = (int)((W.w >> 8) & 255u) * 8;
            const int o2 = (int)((W.w >> 16) & 255u) * 8;
            const uint4* nb = (const uint4*)nhA;
            uint4 r0 = nb[o0 + q], r1 = nb[o1 + q], r2 = nb[o2 + q];
            uint4 e2u = *(const uint4*)&g_e2nTh[1][e][jj];
            uint4 c2u = *(const uint4*)&g_c2Th[0][e][jj];
            __half2 ha = u2h(sIh[1][e]);
            __half2 cp = u2h(sIh[3][e]);
            __half2 bp = u2h(sBPh[0][e]);
            uint4 res;
            res.x = h2u(blend2(ha, u2h(e2u.x), cp, u2h(c2u.x), bp,
                               ws3(w0, w1, w2, r0.x, r1.x, r2.x), H05));
            res.y = h2u(blend2(ha, u2h(e2u.y), cp, u2h(c2u.y), bp,
                               ws3(w0, w1, w2, r0.y, r1.y, r2.y), H05));
            res.z = h2u(blend2(ha, u2h(e2u.z), cp, u2h(c2u.z), bp,
                               ws3(w0, w1, w2, r0.z, r1.z, r2.z), H05));
            res.w = h2u(blend2(ha, u2h(e2u.w), cp, u2h(c2u.w), bp,
                               ws3(w0, w1, w2, r0.w, r1.w, r2.w), H05));
            *(uint4*)&nhB[e][q * 8] = res;
        }
        __syncthreads();   // (3) nhB ready; also orders prior tail sRed reads
                           //     before this unit's sRed writes

        // ---- layer 2: gather nhB + channel accumulation (fp32 acc) ----
        float4 a0 = make_float4(0.f, 0.f, 0.f, 0.f);
        float4 a1 = make_float4(0.f, 0.f, 0.f, 0.f);
        #pragma unroll
        for (int k = 0; k < 2; ++k) {
            const int e = g * 2 + k;
            const uint4 W = sW[1][e];
            const __half2 w0 = u2h(W.x), w1 = u2h(W.y), w2 = u2h(W.z);
            const int o0 = (int)(W.w & 255u) * 8;
            const int o1 = (int)((W.w >> 8) & 255u) * 8;
            const int o2 = (int)((W.w >> 16) & 255u) * 8;
            const uint4* nb = (const uint4*)nhB;
            uint4 r0 = nb[o0 + q], r1 = nb[o1 + q], r2 = nb[o2 + q];
            uint4 e2u = *(const uint4*)&g_e2nTh[2][e][jj];
            uint4 c2u = *(const uint4*)&g_c2Th[1][e][jj];
            __half2 ha = u2h(sIh[2][e]);
            __half2 cp = u2h(sIh[4][e]);
            __half2 bp = u2h(sBPh[1][e]);
            __half2 rA = blend2(ha, u2h(e2u.x), cp, u2h(c2u.x), bp,
                                ws3(w0, w1, w2, r0.x, r1.x, r2.x), H05);
            __half2 rB = blend2(ha, u2h(e2u.y), cp, u2h(c2u.y), bp,
                                ws3(w0, w1, w2, r0.y, r1.y, r2.y), H05);
            __half2 rC = blend2(ha, u2h(e2u.z), cp, u2h(c2u.z), bp,
                                ws3(w0, w1, w2, r0.z, r1.z, r2.z), H05);
            __half2 rD = blend2(ha, u2h(e2u.w), cp, u2h(c2u.w), bp,
                                ws3(w0, w1, w2, r0.w, r1.w, r2.w), H05);
            float2 fA = __half22float2(rA), fB = __half22float2(rB);
            float2 fC = __half22float2(rC), fD = __half22float2(rD);
            a0.x += fA.x; a0.y += fA.y; a0.z += fB.x; a0.w += fB.y;
            a1.x += fC.x; a1.y += fC.y; a1.z += fD.x; a1.w += fD.y;
        }

        // fold the 4 channel-pair groups sharing a warp (8-lane groups)
        a0.x += __shfl_down_sync(0xffffffffu, a0.x, 16);
        a0.y += __shfl_down_sync(0xffffffffu, a0.y, 16);
        a0.z += __shfl_down_sync(0xffffffffu, a0.z, 16);
        a0.w += __shfl_down_sync(0xffffffffu, a0.w, 16);
        a1.x += __shfl_down_sync(0xffffffffu, a1.x, 16);
        a1.y += __shfl_down_sync(0xffffffffu, a1.y, 16);
        a1.z += __shfl_down_sync(0xffffffffu, a1.z, 16);
        a1.w += __shfl_down_sync(0xffffffffu, a1.w, 16);
        a0.x += __shfl_down_sync(0xffffffffu, a0.x, 8);
        a0.y += __shfl_down_sync(0xffffffffu, a0.y, 8);
        a0.z += __shfl_down_sync(0xffffffffu, a0.z, 8);
        a0.w += __shfl_down_sync(0xffffffffu, a0.w, 8);
        a1.x += __shfl_down_sync(0xffffffffu, a1.x, 8);
        a1.y += __shfl_down_sync(0xffffffffu, a1.y, 8);
        a1.z += __shfl_down_sync(0xffffffffu, a1.z, 8);
        a1.w += __shfl_down_sync(0xffffffffu, a1.w, 8);
        const int w = tid >> 5, lane = tid & 31;
        if (lane < 8) {
            sRed[w][lane * 2]     = a0;
            sRed[w][lane * 2 + 1] = a1;
        }
        __syncthreads();   // (4) sRed ready
        if (tid < 16) {
            float4 tot = make_float4(0.f, 0.f, 0.f, 0.f);
            #pragma unroll
            for (int ww = 0; ww < 16; ++ww) {
                float4 t = sRed[ww][tid];
                tot.x += t.x; tot.y += t.y; tot.z += t.z; tot.w += t.w;
            }
            *(float4*)&out[i * B + (unit & 7) * JT + tid * 4] = tot;
        }
    }
}

// ---------------- launch ----------------
extern "C" void kernel_launch(void* const* d_in, const int* in_sizes, int n_in,
                              void* d_out, int out_size)
{
    (void)n_in; (void)out_size;

    const float *e1_0, *e1_1, *e1_2, *e2_0, *e2_1, *e2_2;
    const float *c1_1, *c1_2, *c2_1, *c2_2;
    const float *a_1, *a_2, *b_1, *b_2;
    const float *link0, *link1;

    // Detect input ordering at runtime via element counts (see round-1 note).
    if (in_sizes[4] == 128) {
        // dict insertion order (interleaved per layer)
        e1_0 = (const float*)d_in[0];   e2_0 = (const float*)d_in[1];
        e1_1 = (const float*)d_in[6];   e2_1 = (const float*)d_in[7];
        e1_2 = (const float*)d_in[12];  e2_2 = (const float*)d_in[13];
        c1_1 = (const float*)d_in[8];   c2_1 = (const float*)d_in[9];
        c1_2 = (const float*)d_in[14];  c2_2 = (const float*)d_in[15];
        a_1  = (const float*)d_in[10];  b_1  = (const float*)d_in[11];
        a_2  = (const float*)d_in[16];  b_2  = (const float*)d_in[17];
        link0 = (const float*)d_in[18]; link1 = (const float*)d_in[19];
    } else {
        // function-signature order (grouped)
        e1_0 = (const float*)d_in[0];   e1_1 = (const float*)d_in[1];
        e1_2 = (const float*)d_in[2];
        e2_0 = (const float*)d_in[3];   e2_1 = (const float*)d_in[4];
        e2_2 = (const float*)d_in[5];
        c1_1 = (const float*)d_in[7];   c1_2 = (const float*)d_in[8];
        c2_1 = (const float*)d_in[10];  c2_2 = (const float*)d_in[11];
        a_1  = (const float*)d_in[13];  a_2  = (const float*)d_in[14];
        b_1  = (const float*)d_in[16];  b_2  = (const float*)d_in[17];
        link0 = (const float*)d_in[18]; link1 = (const float*)d_in[19];
    }

    prep_kernel<<<299, 256>>>(e1_0, e1_1, e1_2, e2_0, e2_1, e2_2,
                              c1_1, c1_2, c2_1, c2_2, a_1, a_2, b_1, b_2,
                              link0, link1);

    dim3 blk(8, 64);
    avsl_main_kernel<<<NBLK, blk>>>((float*)d_out);
}